// round 6
// baseline (speedup 1.0000x reference)
#include <cuda_runtime.h>
#include <cuda_bf16.h>
#include <math.h>

// Problem constants: B=4, S=4096, H=2048, E=8, K=2
#define T_TOKENS 16384
#define HDIM     2048
#define NEXP     8
#define TOPK     2
#define H4       (HDIM / 4)   // 512 float4 per row
#define TPW      8            // tokens per warp
#define WARPS    4            // warps per CTA
#define NITER    (H4 / 32)    // 16 strided iterations per lane

// Zero-initialized at module load; last block re-zeros after each use so
// every graph replay sees a clean state (deterministic).
__device__ int g_counts[NEXP];
__device__ unsigned int g_done;

// x streams GMEM->SMEM via per-lane cp.async double buffer: while stage s is
// consumed (LDS, 29 cyc), stage s+1's 8 LDGSTS are in flight. Each lane only
// touches its own 16B slots, so commit_group/wait_group per-thread ordering
// is sufficient -- no barriers in the main loop.
__global__ __launch_bounds__(128, 4)
void router_kernel(const float* __restrict__ x,
                   const float* __restrict__ gate_w,
                   float* __restrict__ out) {
    // [warp][stage][tok][lane] float4 = 32 KB per CTA
    __shared__ float4 s_x[WARPS][2][TPW][32];
    __shared__ int s_counts[NEXP];
    if (threadIdx.x < NEXP) s_counts[threadIdx.x] = 0;
    __syncthreads();

    const int lane        = threadIdx.x & 31;
    const int wid         = threadIdx.x >> 5;
    const int warp_global = blockIdx.x * WARPS + wid;
    const int t0          = warp_global * TPW;

    const float4* __restrict__ x4 = (const float4*)x;
    const float4* __restrict__ w4 = (const float4*)gate_w;
    const float4* __restrict__ xrow = x4 + (size_t)t0 * H4;

    // Per-lane smem base (stage 0, tok 0, this lane). Strides in bytes:
    // stage = TPW*32*16 = 4096, tok = 32*16 = 512.
    unsigned int s_base =
        (unsigned int)__cvta_generic_to_shared(&s_x[wid][0][0][lane]);

    // a[tok*8 + exp] accumulators (64 regs)
    float a[TPW * NEXP];
    #pragma unroll
    for (int p = 0; p < TPW * NEXP; p++) a[p] = 0.0f;

    // Issue one stage: 8 independent 16B async copies (one per token).
    #define ISSUE_STAGE(IT)                                                  \
    do {                                                                     \
        const unsigned int dst = s_base + (((IT) & 1) ? 4096u : 0u);         \
        const float4* src = xrow + (lane + 32 * (IT));                       \
        _Pragma("unroll")                                                    \
        for (int m = 0; m < TPW; m++)                                        \
            asm volatile("cp.async.cg.shared.global [%0], [%1], 16;"         \
                         :: "r"(dst + (unsigned)(m * 512)),                  \
                            "l"(src + (size_t)m * H4) : "memory");           \
        asm volatile("cp.async.commit_group;" ::: "memory");                 \
    } while (0)

    ISSUE_STAGE(0);

    #pragma unroll 2
    for (int it = 0; it < NITER; it++) {
        if (it + 1 < NITER) {
            ISSUE_STAGE(it + 1);
            asm volatile("cp.async.wait_group 1;" ::: "memory");
        } else {
            asm volatile("cp.async.wait_group 0;" ::: "memory");
        }

        // Pull this stage's 8 token-vectors out of smem (8 LDS.128).
        float4 xv[TPW];
        #pragma unroll
        for (int m = 0; m < TPW; m++)
            xv[m] = s_x[wid][it & 1][m][lane];

        const int i = lane + 32 * it;
        #pragma unroll
        for (int e = 0; e < NEXP; e++) {
            float4 wv = __ldg(w4 + (size_t)e * H4 + i);
            #pragma unroll
            for (int m = 0; m < TPW; m++) {
                a[m * NEXP + e] = fmaf(xv[m].x, wv.x, a[m * NEXP + e]);
                a[m * NEXP + e] = fmaf(xv[m].y, wv.y, a[m * NEXP + e]);
                a[m * NEXP + e] = fmaf(xv[m].z, wv.z, a[m * NEXP + e]);
                a[m * NEXP + e] = fmaf(xv[m].w, wv.w, a[m * NEXP + e]);
            }
        }
    }
    #undef ISSUE_STAGE

    // Halving warp reduction over 64 partial sums (static indices only).
    // After 5 levels, lane L holds a[0]=sum(group 2L), a[1]=sum(group 2L+1),
    // where group = tok*8 + exp.
#define RED_LEVEL(O, L2)                                                   \
    _Pragma("unroll")                                                      \
    for (int j = 0; j < (L2); j++) {                                       \
        float mine  = (lane & (O)) ? a[j + (L2)] : a[j];                   \
        float yours = (lane & (O)) ? a[j] : a[j + (L2)];                   \
        a[j] = mine + __shfl_xor_sync(0xFFFFFFFFu, yours, (O));            \
    }
    RED_LEVEL(16, 32)
    RED_LEVEL(8, 16)
    RED_LEVEL(4, 8)
    RED_LEVEL(2, 4)
    RED_LEVEL(1, 2)
#undef RED_LEVEL

    // Quad gather: token q's 8 logits live as pairs {2L,2L+1} in lanes
    // L = 4q..4q+3. Rebuild l[8] per token.
    const int tok = lane >> 2;
    float l[NEXP];
    #pragma unroll
    for (int q = 0; q < 4; q++) {
        l[2 * q]     = __shfl_sync(0xFFFFFFFFu, a[0], (tok << 2) | q);
        l[2 * q + 1] = __shfl_sync(0xFFFFFFFFu, a[1], (tok << 2) | q);
    }

    if ((lane & 3) == 0) {
        const int t = t0 + tok;

        // top-1 (strict > keeps lowest index on tie, matching jax top_k)
        float m1 = l[0]; int i1 = 0;
        #pragma unroll
        for (int e = 1; e < NEXP; e++)
            if (l[e] > m1) { m1 = l[e]; i1 = e; }
        // top-2
        float m2 = -INFINITY; int i2 = 0;
        #pragma unroll
        for (int e = 0; e < NEXP; e++)
            if (e != i1 && l[e] > m2) { m2 = l[e]; i2 = e; }

        // renormalized top-2 softmax weights
        float e2  = __expf(m2 - m1);    // <= 1, numerically safe
        float inv = 1.0f / (1.0f + e2);

        out[(size_t)t * TOPK + 0] = inv;
        out[(size_t)t * TOPK + 1] = e2 * inv;
        out[(size_t)T_TOKENS * TOPK + (size_t)t * TOPK + 0] = (float)i1;
        out[(size_t)T_TOKENS * TOPK + (size_t)t * TOPK + 1] = (float)i2;

        atomicAdd(&s_counts[i1], 1);
        atomicAdd(&s_counts[i2], 1);
    }

    __syncthreads();
    if (threadIdx.x < NEXP)
        atomicAdd(&g_counts[threadIdx.x], s_counts[threadIdx.x]);
    __threadfence();
    __syncthreads();

    // Last block computes the aux loss and resets global state.
    if (threadIdx.x == 0) {
        unsigned int prev = atomicAdd(&g_done, 1u);
        if (prev == gridDim.x - 1) {
            volatile int* vc = (volatile int*)g_counts;
            float mpe[NEXP];
            float mu = 0.0f;
            #pragma unroll
            for (int e = 0; e < NEXP; e++) {
                mpe[e] = (float)vc[e] / (float)T_TOKENS;
                mu += mpe[e];
            }
            mu *= (1.0f / NEXP);
            float v = 0.0f;
            #pragma unroll
            for (int e = 0; e < NEXP; e++) {
                float d = mpe[e] - mu;
                v += d * d;
            }
            v *= (1.0f / (NEXP - 1));   // unbiased variance (ddof=1)
            out[(size_t)T_TOKENS * TOPK * 2] = v * (float)NEXP;

            // Reset for the next graph replay.
            #pragma unroll
            for (int e = 0; e < NEXP; e++) g_counts[e] = 0;
            g_done = 0u;
        }
    }
}

extern "C" void kernel_launch(void* const* d_in, const int* in_sizes, int n_in,
                              void* d_out, int out_size) {
    const float* x      = (const float*)d_in[0];   // (B,S,H) = (T, H)
    const float* gate_w = (const float*)d_in[1];   // (E, H)
    float* out = (float*)d_out;

    router_kernel<<<512, 128>>>(x, gate_w, out);
}

// round 7
// speedup vs baseline: 1.9733x; 1.9733x over previous
#include <cuda_runtime.h>
#include <cuda_bf16.h>
#include <math.h>

// Problem constants: B=4, S=4096, H=2048, E=8, K=2
#define T_TOKENS 16384
#define HDIM     2048
#define NEXP     8
#define TOPK     2
#define H4       (HDIM / 4)   // 512 float4 per row
#define TPW      8            // tokens per warp
#define NITER    (H4 / 16)    // 32: each half-warp covers 16 float4 per iter

// Zero-initialized at module load; last block re-zeros after each use so
// every graph replay sees a clean state (deterministic).
__device__ int g_counts[NEXP];
__device__ unsigned int g_done;

// Layout: one warp = 8 tokens. Half-warp expert split: lanes 0-15 own experts
// 0-3, lanes 16-31 own experts 4-7; both halves read the same x H-slice
// (duplicate addresses dedup in L1 -> no extra traffic). This frees 64 regs
// vs the full-expert layout, spent on a register double-buffer that keeps 8
// x-loads in flight during every FMA stretch (load duty cycle ~= 1).
// 1024 CTAs x 64 threads = 2048 warps = T/8 groups, single balanced wave.
__global__ __launch_bounds__(64, 8)
void router_kernel(const float* __restrict__ x,
                   const float* __restrict__ gate_w,
                   float* __restrict__ out) {
    __shared__ int s_counts[NEXP];
    if (threadIdx.x < NEXP) s_counts[threadIdx.x] = 0;
    __syncthreads();

    const int lane        = threadIdx.x & 31;
    const int l4          = lane & 15;        // position within half-warp
    const int ebase       = (lane >> 4) * 4;  // this half-warp's expert base
    const int warp_global = (blockIdx.x * blockDim.x + threadIdx.x) >> 5;
    const int t0          = warp_global * TPW;

    const float4* __restrict__ x4 = (const float4*)x;
    const float4* __restrict__ w4 = (const float4*)gate_w;
    const float4* __restrict__ xb0 = x4 + (size_t)t0 * H4 + l4;  // token 0, iter 0

    // acc[m*4 + j] : token m, local expert j (32 regs)
    float acc[TPW * 4];
    #pragma unroll
    for (int p = 0; p < TPW * 4; p++) acc[p] = 0.0f;

    float4 xa[TPW], xb[TPW];

    // Prologue: load iteration 0's x into buffer A.
    #pragma unroll
    for (int m = 0; m < TPW; m++)
        xa[m] = __ldg(xb0 + (size_t)m * H4);

    // One step: prefetch x for (IT+1) into NXT, compute iteration IT from CUR.
#define STEP(CUR, NXT, IT)                                                   \
    do {                                                                     \
        const int _nit = (IT) + 1;                                           \
        if (_nit < NITER) {                                                  \
            _Pragma("unroll")                                                \
            for (int m = 0; m < TPW; m++)                                    \
                NXT[m] = __ldg(xb0 + (size_t)m * H4 + 16 * _nit);            \
        }                                                                    \
        const int _i = l4 + 16 * (IT);                                       \
        float4 wv[4];                                                        \
        _Pragma("unroll")                                                    \
        for (int j = 0; j < 4; j++)                                          \
            wv[j] = __ldg(w4 + (size_t)(ebase + j) * H4 + _i);               \
        _Pragma("unroll")                                                    \
        for (int j = 0; j < 4; j++)                                          \
            _Pragma("unroll")                                                \
            for (int m = 0; m < TPW; m++) {                                  \
                acc[m * 4 + j] = fmaf(CUR[m].x, wv[j].x, acc[m * 4 + j]);    \
                acc[m * 4 + j] = fmaf(CUR[m].y, wv[j].y, acc[m * 4 + j]);    \
                acc[m * 4 + j] = fmaf(CUR[m].z, wv[j].z, acc[m * 4 + j]);    \
                acc[m * 4 + j] = fmaf(CUR[m].w, wv[j].w, acc[m * 4 + j]);    \
            }                                                                \
    } while (0)

    #pragma unroll 1
    for (int it2 = 0; it2 < NITER / 2; it2++) {
        STEP(xa, xb, 2 * it2);
        STEP(xb, xa, 2 * it2 + 1);
    }
#undef STEP

    // Halving reduction over 32 partials within each 16-lane half-warp
    // (static indices only; offsets <=8 never cross the half-warp).
    // Result: lane l4 holds a[0] = sum(group 2*l4), a[1] = sum(group 2*l4+1),
    // group = tok*4 + local_expert.
    float a[32];
    #pragma unroll
    for (int p = 0; p < 32; p++) a[p] = acc[p];
#define RED_LEVEL(O, L2)                                                   \
    _Pragma("unroll")                                                      \
    for (int j = 0; j < (L2); j++) {                                       \
        float mine  = (lane & (O)) ? a[j + (L2)] : a[j];                   \
        float yours = (lane & (O)) ? a[j] : a[j + (L2)];                   \
        a[j] = mine + __shfl_xor_sync(0xFFFFFFFFu, yours, (O));            \
    }
    RED_LEVEL(8, 16)
    RED_LEVEL(4, 8)
    RED_LEVEL(2, 4)
    RED_LEVEL(1, 2)
#undef RED_LEVEL

    // Lane (hw, l4) holds token l4>>1, experts ebase + 2*(l4&1) + {0,1}.
    // Gather token t's 8 logits: lanes 2t, 2t+1 (experts 0-3) and
    // 16+2t, 17+2t (experts 4-7). Every lane rebuilds its token t = lane>>2.
    const int tok = lane >> 2;
    float l[NEXP];
    l[0] = __shfl_sync(0xFFFFFFFFu, a[0], 2 * tok);
    l[1] = __shfl_sync(0xFFFFFFFFu, a[1], 2 * tok);
    l[2] = __shfl_sync(0xFFFFFFFFu, a[0], 2 * tok + 1);
    l[3] = __shfl_sync(0xFFFFFFFFu, a[1], 2 * tok + 1);
    l[4] = __shfl_sync(0xFFFFFFFFu, a[0], 16 + 2 * tok);
    l[5] = __shfl_sync(0xFFFFFFFFu, a[1], 16 + 2 * tok);
    l[6] = __shfl_sync(0xFFFFFFFFu, a[0], 17 + 2 * tok);
    l[7] = __shfl_sync(0xFFFFFFFFu, a[1], 17 + 2 * tok);

    if ((lane & 3) == 0) {
        const int t = t0 + tok;

        // top-1 (strict > keeps lowest index on tie, matching jax top_k)
        float m1 = l[0]; int i1 = 0;
        #pragma unroll
        for (int e = 1; e < NEXP; e++)
            if (l[e] > m1) { m1 = l[e]; i1 = e; }
        // top-2
        float m2 = -INFINITY; int i2 = 0;
        #pragma unroll
        for (int e = 0; e < NEXP; e++)
            if (e != i1 && l[e] > m2) { m2 = l[e]; i2 = e; }

        // renormalized top-2 softmax weights
        float e2  = __expf(m2 - m1);    // <= 1, numerically safe
        float inv = 1.0f / (1.0f + e2);

        out[(size_t)t * TOPK + 0] = inv;
        out[(size_t)t * TOPK + 1] = e2 * inv;
        out[(size_t)T_TOKENS * TOPK + (size_t)t * TOPK + 0] = (float)i1;
        out[(size_t)T_TOKENS * TOPK + (size_t)t * TOPK + 1] = (float)i2;

        atomicAdd(&s_counts[i1], 1);
        atomicAdd(&s_counts[i2], 1);
    }

    __syncthreads();
    if (threadIdx.x < NEXP)
        atomicAdd(&g_counts[threadIdx.x], s_counts[threadIdx.x]);
    __threadfence();
    __syncthreads();

    // Last block computes the aux loss and resets global state.
    if (threadIdx.x == 0) {
        unsigned int prev = atomicAdd(&g_done, 1u);
        if (prev == gridDim.x - 1) {
            volatile int* vc = (volatile int*)g_counts;
            float mpe[NEXP];
            float mu = 0.0f;
            #pragma unroll
            for (int e = 0; e < NEXP; e++) {
                mpe[e] = (float)vc[e] / (float)T_TOKENS;
                mu += mpe[e];
            }
            mu *= (1.0f / NEXP);
            float v = 0.0f;
            #pragma unroll
            for (int e = 0; e < NEXP; e++) {
                float d = mpe[e] - mu;
                v += d * d;
            }
            v *= (1.0f / (NEXP - 1));   // unbiased variance (ddof=1)
            out[(size_t)T_TOKENS * TOPK * 2] = v * (float)NEXP;

            // Reset for the next graph replay.
            #pragma unroll
            for (int e = 0; e < NEXP; e++) g_counts[e] = 0;
            g_done = 0u;
        }
    }
}

extern "C" void kernel_launch(void* const* d_in, const int* in_sizes, int n_in,
                              void* d_out, int out_size) {
    const float* x      = (const float*)d_in[0];   // (B,S,H) = (T, H)
    const float* gate_w = (const float*)d_in[1];   // (E, H)
    float* out = (float*)d_out;

    router_kernel<<<1024, 64>>>(x, gate_w, out);
}